// round 14
// baseline (speedup 1.0000x reference)
#include <cuda_runtime.h>
#include <cuda_bf16.h>
#include <cuda_fp16.h>
#include <math.h>

#define C_DIM   2048
#define N_HEADS 16
#define HD      128
#define B_SZ    2
#define T_SZ    2048
#define BT      (B_SZ * T_SZ)

typedef unsigned long long u64;
typedef unsigned int u32;

#define LOG2E 1.4426950408889634f

// ---------------- packed f32x2 helpers (SASS FFMA2) -------------------------
__device__ __forceinline__ u64 pk2(float lo, float hi) {
    u64 r; asm("mov.b64 %0, {%1, %2};" : "=l"(r) : "f"(lo), "f"(hi)); return r;
}
__device__ __forceinline__ void fma2(u64& d, u64 a, u64 b) {
    asm("fma.rn.f32x2 %0, %1, %2, %0;" : "+l"(d) : "l"(a), "l"(b));
}
__device__ __forceinline__ float2 upk2(u64 v) {
    float2 f; asm("mov.b64 {%0, %1}, %2;" : "=f"(f.x), "=f"(f.y) : "l"(v)); return f;
}

// ---------------- mma.sync / ldmatrix / cp.async helpers --------------------
__device__ __forceinline__ u32 smem_u32(const void* p) {
    u32 a; asm("{ .reg .u64 t; cvta.to.shared.u64 t, %1; cvt.u32.u64 %0, t; }"
               : "=r"(a) : "l"(p));
    return a;
}
#define LDSM_X4(r0, r1, r2, r3, addr) \
    asm volatile("ldmatrix.sync.aligned.m8n8.x4.shared.b16 {%0,%1,%2,%3}, [%4];" \
        : "=r"(r0), "=r"(r1), "=r"(r2), "=r"(r3) : "r"(addr))
#define LDSM_X4T(r0, r1, r2, r3, addr) \
    asm volatile("ldmatrix.sync.aligned.m8n8.x4.trans.shared.b16 {%0,%1,%2,%3}, [%4];" \
        : "=r"(r0), "=r"(r1), "=r"(r2), "=r"(r3) : "r"(addr))
#define MMA16816H(d, a, b) \
    asm volatile("mma.sync.aligned.m16n8k16.row.col.f32.f16.f16.f32 " \
        "{%0,%1,%2,%3}, {%4,%5,%6,%7}, {%8,%9}, {%0,%1,%2,%3};" \
        : "+f"((d)[0]), "+f"((d)[1]), "+f"((d)[2]), "+f"((d)[3]) \
        : "r"((a)[0]), "r"((a)[1]), "r"((a)[2]), "r"((a)[3]), "r"((b)[0]), "r"((b)[1]))
#define CP16(daddr, gsrc) \
    asm volatile("cp.async.cg.shared.global [%0], [%1], 16;" \
        :: "r"(daddr), "l"(gsrc) : "memory")
#define CP_COMMIT() asm volatile("cp.async.commit_group;" ::: "memory")
#define CP_WAIT0()  asm volatile("cp.async.wait_group 0;" ::: "memory")
#define CP_WAIT1()  asm volatile("cp.async.wait_group 1;" ::: "memory")

__device__ __forceinline__ u32 pack_h2(__half a, __half b) {
    __half2 t = __halves2half2(a, b);
    return *(u32*)&t;
}
__device__ __forceinline__ float ex2f(float x) {
    float r; asm("ex2.approx.f32 %0, %1;" : "=f"(r) : "f"(x)); return r;
}
__device__ __forceinline__ u32 cvtf16x2(float lo, float hi) {
    u32 r; asm("cvt.rn.f16x2.f32 %0, %1, %2;" : "=r"(r) : "f"(hi), "f"(lo)); return r;
}

// ---------------- scratch ----------------------------------------------------
__device__ __align__(16) float g_ks[BT * HD];
__device__ __align__(16) float g_vs[BT * HD];
__device__ float g_gv [BT];
__device__ int   g_cnt[N_HEADS];
__device__ int   g_list[N_HEADS * BT];
__device__ __align__(16) __half g_xh[BT * C_DIM];     // x f16 (single)
__device__ __align__(16) __half g_wh[C_DIM * C_DIM];  // Wq f16 hi
__device__ __align__(16) __half g_wl[C_DIM * C_DIM];  // Wq f16 lo
__device__ __align__(16) __half g_qh[BT * C_DIM];     // scaled Q f16 (single)
__device__ __align__(16) __half g_kh[BT * HD];        // K f16 hi
__device__ __align__(16) __half g_kl[BT * HD];        // K f16 lo
__device__ __align__(16) __half g_vh[BT * HD];        // V f16

// ---------------- K0: zero counters + K/V accumulators -----------------------
__global__ __launch_bounds__(256) void zero_kernel() {
    const int i = blockIdx.x * 256 + threadIdx.x;
    const float4 z = make_float4(0.f, 0.f, 0.f, 0.f);
    if (i < BT * HD / 4) { ((float4*)g_ks)[i] = z; ((float4*)g_vs)[i] = z; }
    if (blockIdx.x == 0 && threadIdx.x < N_HEADS) g_cnt[threadIdx.x] = 0;
}

// ---------------- K1: split fp32 -> f16 hi/lo (Q weights) ---------------------
__global__ __launch_bounds__(256) void cvt_kernel(
    const float* __restrict__ src, __half* __restrict__ hi,
    __half* __restrict__ lo, int n4)
{
    const int i = blockIdx.x * 256 + threadIdx.x;
    if (i >= n4) return;
    const float4 v = ((const float4*)src)[i];
    const float f[4] = {v.x, v.y, v.z, v.w};
    __half h[4], l[4];
#pragma unroll
    for (int j = 0; j < 4; j++) {
        h[j] = __float2half(f[j]);
        l[j] = __float2half(f[j] - __half2float(h[j]));
    }
    u32* H = (u32*)hi; u32* L = (u32*)lo;
    H[2*i]   = pack_h2(h[0], h[1]);
    H[2*i+1] = pack_h2(h[2], h[3]);
    L[2*i]   = pack_h2(l[0], l[1]);
    L[2*i+1] = pack_h2(l[2], l[3]);
}

// ---------------- K2: fused x f16 conversion + gating -------------------------
#define GT   16
#define XSTR 144

__global__ __launch_bounds__(256) void xcvt_gate_kernel(
    const float* __restrict__ x, const float* __restrict__ Wg)
{
    __shared__ float Xs[GT * XSTR];
    __shared__ float Ws[16 * 128];
    const int tid = threadIdx.x;
    const int t0 = blockIdx.x * GT;

    float acc[N_HEADS];
#pragma unroll
    for (int h = 0; h < N_HEADS; h++) acc[h] = 0.0f;

    for (int kc = 0; kc < C_DIM / 128; kc++) {
        __syncthreads();
        for (int u = tid; u < 512; u += 256) {
            const int h = u >> 5, c4 = u & 31;
            *(float4*)&Ws[h * 128 + c4 * 4] =
                *(const float4*)&Wg[(size_t)h * C_DIM + kc * 128 + c4 * 4];
        }
        for (int u = tid; u < GT * 32; u += 256) {
            const int r = u >> 5, c4 = u & 31;
            const size_t g = (size_t)(t0 + r) * C_DIM + kc * 128 + c4 * 4;
            const float4 v = *(const float4*)&x[g];
            *(float4*)&Xs[r * XSTR + c4 * 4] = v;
            ((u32*)&g_xh[g])[0] = cvtf16x2(v.x, v.y);
            ((u32*)&g_xh[g])[1] = cvtf16x2(v.z, v.w);
        }
        __syncthreads();
        const int r = tid >> 4, i = tid & 15;
#pragma unroll
        for (int k = 0; k < 8; k++) {
            const float xv = Xs[r * XSTR + k * 16 + i];
#pragma unroll
            for (int h = 0; h < N_HEADS; h++)
                acc[h] += xv * Ws[h * 128 + k * 16 + i];
        }
    }
#pragma unroll
    for (int off = 1; off < 16; off <<= 1) {
#pragma unroll
        for (int h = 0; h < N_HEADS; h++)
            acc[h] += __shfl_xor_sync(0xffffffffu, acc[h], off);
    }
    if ((tid & 15) == 0) {
        const int t = t0 + (tid >> 4);
        float mx = acc[0]; int bi = 0;
#pragma unroll
        for (int h = 1; h < N_HEADS; h++)
            if (acc[h] > mx) { mx = acc[h]; bi = h; }
        float s = 0.0f;
#pragma unroll
        for (int h = 0; h < N_HEADS; h++) s += expf(acc[h] - mx);
        g_gv[t] = 1.0f / s;
        const int pos = atomicAdd(&g_cnt[bi], 1);
        g_list[bi * BT + pos] = t;
    }
}

// ---------------- K3: Q projection, f16 2-pass + cp.async double-buffer -------
// D = xh*(Wh + Wl). CTA 128x128, K-chunk 32, warp tile 64x32, paired B X4.
#define QSTR 40
#define QP_ASZB (128 * QSTR * 2)        // 10240 B per array
#define QP_STAGEB (3 * QP_ASZB)         // A, Bh, Bl = 30720 B
#define QP_SMEM (2 * QP_STAGEB)         // 61440 B

__global__ __launch_bounds__(256, 2) void qproj_mma_kernel()
{
    extern __shared__ __half qsm[];
    const u32 sb = smem_u32(qsm);

    const int tid = threadIdx.x, lane = tid & 31, wid = tid >> 5;
    const int wm = (wid >> 2) * 64;
    const int wn = (wid & 3) * 32;
    const int m0 = blockIdx.y * 128, n0 = blockIdx.x * 128;

    float acc[4][4][4];
#pragma unroll
    for (int i = 0; i < 4; i++)
#pragma unroll
        for (int j = 0; j < 4; j++)
#pragma unroll
            for (int r = 0; r < 4; r++) acc[i][j][r] = 0.0f;

    const int q = lane >> 3, r8 = lane & 7;
    const int arow = (q & 1) * 8 + r8, acolq = (q >> 1) * 8;
    const int b4row = (lane >> 4) * 8 + (lane & 7);     // paired-X4 B addressing
    const int b4colq = ((lane >> 3) & 1) * 8;

    auto issue_stage = [&](int kt, int s) {
#pragma unroll
        for (int v = 0; v < 6; v++) {
            const int u = tid + v * 256;
            const int arr = u >> 9;                      // 0=A,1=Bh,2=Bl
            const int idx = u & 511;
            const int rr = idx >> 2, cc = (idx & 3) * 8;
            const __half* gp;
            if (arr == 0)      gp = g_xh + (size_t)(m0 + rr) * C_DIM + kt + cc;
            else if (arr == 1) gp = g_wh + (size_t)(n0 + rr) * C_DIM + kt + cc;
            else               gp = g_wl + (size_t)(n0 + rr) * C_DIM + kt + cc;
            CP16(sb + s * QP_STAGEB + arr * QP_ASZB + (rr * QSTR + cc) * 2, gp);
        }
        CP_COMMIT();
    };

    issue_stage(0, 0);

    const int NIT = C_DIM / 32;
    for (int i = 0; i < NIT; i++) {
        const int s = i & 1;
        if (i + 1 < NIT) { issue_stage((i + 1) * 32, s ^ 1); CP_WAIT1(); }
        else             { CP_WAIT0(); }
        __syncthreads();

        const u32 sA  = sb + s * QP_STAGEB;
        const u32 sBh = sA + QP_ASZB;
        const u32 sBl = sBh + QP_ASZB;

#pragma unroll
        for (int ks = 0; ks < 2; ks++) {
            u32 a[4][4];
#pragma unroll
            for (int mt = 0; mt < 4; mt++) {
                const u32 off = ((wm + mt * 16 + arow) * QSTR + ks * 16 + acolq) * 2;
                LDSM_X4(a[mt][0], a[mt][1], a[mt][2], a[mt][3], sA + off);
            }
#pragma unroll
            for (int pj = 0; pj < 2; pj++) {             // n-tile pairs {0,1},{2,3}
                u32 bh[4], bl[4];
                const u32 off = ((wn + pj * 16 + b4row) * QSTR + ks * 16 + b4colq) * 2;
                LDSM_X4(bh[0], bh[1], bh[2], bh[3], sBh + off);
                LDSM_X4(bl[0], bl[1], bl[2], bl[3], sBl + off);
#pragma unroll
                for (int mt = 0; mt < 4; mt++) {
                    MMA16816H(acc[mt][2*pj],   a[mt], bh);
                    MMA16816H(acc[mt][2*pj+1], a[mt], bh + 2);
                    MMA16816H(acc[mt][2*pj],   a[mt], bl);
                    MMA16816H(acc[mt][2*pj+1], a[mt], bl + 2);
                }
            }
        }
        __syncthreads();
    }

    const float SC = 0.08838834764831845f;  // 1/sqrt(128)
    const int er = lane >> 2, ec = (lane & 3) * 2;
#pragma unroll
    for (int mt = 0; mt < 4; mt++) {
        const size_t row = (size_t)(m0 + wm + mt * 16 + er);
#pragma unroll
        for (int nt = 0; nt < 4; nt++) {
            const int col = n0 + wn + nt * 8 + ec;
#pragma unroll
            for (int half = 0; half < 2; half++) {
                const float v0 = acc[mt][nt][half * 2 + 0] * SC;
                const float v1 = acc[mt][nt][half * 2 + 1] * SC;
                *(u32*)&g_qh[(row + half * 8) * C_DIM + col] = cvtf16x2(v0, v1);
            }
        }
    }
}

// ---------------- K4: grouped K/V projection, split-K=4 + atomics -------------
#define KV_SPLITS 4
#define KV_KCH (C_DIM / KV_SPLITS)

__global__ __launch_bounds__(256) void kvproj_kernel(
    const float* __restrict__ x, const float* __restrict__ Wqkv)
{
    const int h = blockIdx.y;
    const int kv = blockIdx.z & 1, sp = blockIdx.z >> 1;
    const int cnt = g_cnt[h];
    const int m0 = blockIdx.x * 32;
    if (m0 >= cnt) return;

    __shared__ float As[16][32];
    __shared__ float Bs[16][128];
    const int tid = threadIdx.x;
    const int blr = tid >> 2, blc = (tid & 3) << 2;
    const int tx = tid & 31, ty = tid >> 5;

    const int* lst = g_list + h * BT;
    int tokA = 0;
    if (tid < 128) tokA = lst[min(m0 + (tid >> 2), cnt - 1)];
    const float* Bp = Wqkv + (size_t)(C_DIM * (1 + kv) + h * HD) * C_DIM;

    u64 acc2[4][2];
#pragma unroll
    for (int i = 0; i < 4; i++) { acc2[i][0] = 0ULL; acc2[i][1] = 0ULL; }

    const int k0 = sp * KV_KCH;
    for (int kt = k0; kt < k0 + KV_KCH; kt += 16) {
        float4 a0 = make_float4(0.f, 0.f, 0.f, 0.f);
        if (tid < 128)
            a0 = *(const float4*)(x + (size_t)tokA * C_DIM + kt + blc);
        const float4 b0 = *(const float4*)(Bp + (size_t)blr        * C_DIM + kt + blc);
        const float4 b1 = *(const float4*)(Bp + (size_t)(blr + 64) * C_DIM + kt + blc);
        __syncthreads();
        if (tid < 128) {
            const int ar = tid >> 2;
            As[blc+0][ar] = a0.x; As[blc+1][ar] = a0.y;
            As[blc+2][ar] = a0.z; As[blc+3][ar] = a0.w;
        }
        Bs[blc+0][blr] = b0.x; Bs[blc+1][blr] = b0.y; Bs[blc+2][blr] = b0.z; Bs[blc+3][blr] = b0.w;
        Bs[blc+0][blr+64] = b1.x; Bs[blc+1][blr+64] = b1.y; Bs[blc+2][blr+64] = b1.z; Bs[blc+3][blr+64] = b1.w;
        __syncthreads();
#pragma unroll
        for (int k = 0; k < 16; k++) {
            const float4 av = *(const float4*)&As[k][ty * 4];
            const float4 bv = *(const float4*)&Bs[k][tx * 4];
            const u64 b20 = pk2(bv.x, bv.y), b21 = pk2(bv.z, bv.w);
            const float aa[4] = {av.x, av.y, av.z, av.w};
#pragma unroll
            for (int i = 0; i < 4; i++) {
                const u64 a2 = pk2(aa[i], aa[i]);
                fma2(acc2[i][0], a2, b20);
                fma2(acc2[i][1], a2, b21);
            }
        }
    }
    float* dst = kv ? g_vs : g_ks;
#pragma unroll
    for (int i = 0; i < 4; i++) {
        const int m = m0 + ty * 4 + i;
        if (m < cnt) {
            const int tok = lst[m];
            const float sc = kv ? g_gv[tok] : 1.0f;
            const float2 c0 = upk2(acc2[i][0]), c1 = upk2(acc2[i][1]);
            float* d = dst + (size_t)tok * HD + tx * 4;
            atomicAdd(d + 0, c0.x * sc);
            atomicAdd(d + 1, c0.y * sc);
            atomicAdd(d + 2, c1.x * sc);
            atomicAdd(d + 3, c1.y * sc);
        }
    }
}

// ---------------- K4b: K fp32 -> f16 hi/lo ; V fp32 -> f16 --------------------
__global__ __launch_bounds__(256) void kvcvt_kernel() {
    const int i = blockIdx.x * 256 + threadIdx.x;
    if (i >= BT * HD / 4) return;
    {
        const float4 v = ((const float4*)g_ks)[i];
        const float f[4] = {v.x, v.y, v.z, v.w};
        __half h[4], l[4];
#pragma unroll
        for (int j = 0; j < 4; j++) {
            h[j] = __float2half(f[j]);
            l[j] = __float2half(f[j] - __half2float(h[j]));
        }
        ((u32*)g_kh)[2*i]   = pack_h2(h[0], h[1]);
        ((u32*)g_kh)[2*i+1] = pack_h2(h[2], h[3]);
        ((u32*)g_kl)[2*i]   = pack_h2(l[0], l[1]);
        ((u32*)g_kl)[2*i+1] = pack_h2(l[2], l[3]);
    }
    {
        const float4 v = ((const float4*)g_vs)[i];
        ((u32*)g_vh)[2*i]   = cvtf16x2(v.x, v.y);
        ((u32*)g_vh)[2*i+1] = cvtf16x2(v.z, v.w);
    }
}

// ---------------- K5: tensor-core causal flash MQA attention ------------------
// BQ=128, 8 warps, BK=64, cp.async double-buffered K/V.
// S = Qf16 * (Kh + Kl), 2-pass. P f16. V f16. Row sums via ones-MMA.
#define ASTR 136
#define AQ_B   (128 * ASTR * 2)          // Q (single f16)
#define AST_B  (64 * ASTR * 2)
#define ASTG_B (3 * AST_B)               // Kh, Kl, Vh
#define ATTN_SMEM (AQ_B + 2 * ASTG_B)    // 139264

__global__ __launch_bounds__(256, 1) void attn_mma_kernel(float* __restrict__ out)
{
    extern __shared__ char sbuf[];
    const u32 sb = smem_u32(sbuf);
    const u32 sQ = sb;
    const u32 stage0 = sb + AQ_B;

    const int b  = blockIdx.z, h = blockIdx.y;
    const int qt = gridDim.x - 1 - blockIdx.x;
    const int q0 = qt * 128;
    const int tid = threadIdx.x, lane = tid & 31, wid = tid >> 5;
    const int wm = wid * 16;

    for (int u = tid; u < 2048; u += 256) {
        const int r = u >> 4, c = (u & 15) * 8;
        const size_t g = (size_t)(b * T_SZ + q0 + r) * C_DIM + h * HD + c;
        *(uint4*)(sbuf + (r * ASTR + c) * 2) = *(const uint4*)&g_qh[g];
    }

    const int qq = lane >> 3, r8 = lane & 7;
    const int arow = (qq & 1) * 8 + r8, acolq = (qq >> 1) * 8;
    const int b4row = (lane >> 4) * 8 + (lane & 7);
    const int b4colq = ((lane >> 3) & 1) * 8;
    const int er = lane >> 2, ec = (lane & 3) * 2;

    float m0 = -1e30f, m1 = -1e30f;
    float La[4] = {0.f, 0.f, 0.f, 0.f};
    float O[16][4];
#pragma unroll
    for (int t = 0; t < 16; t++)
#pragma unroll
        for (int r = 0; r < 4; r++) O[t][r] = 0.f;

    const u32 ones2 = 0x3C003C00u;
    const u32 onesfrag[2] = {ones2, ones2};

    const int ktmax = 2 * qt + 1;

    auto issue_kv = [&](int kt, int s) {
#pragma unroll
        for (int v = 0; v < 12; v++) {
            const int u = tid + v * 256;
            const int arr = u >> 10;              // 0=Kh,1=Kl,2=Vh
            const int idx = u & 1023;
            const int r = idx >> 4, c = (idx & 15) * 8;
            const size_t g = (size_t)(b * T_SZ + kt * 64 + r) * HD + c;
            const void* gp = (arr == 0) ? (const void*)&g_kh[g]
                           : (arr == 1) ? (const void*)&g_kl[g]
                                        : (const void*)&g_vh[g];
            CP16(stage0 + s * ASTG_B + arr * AST_B + (r * ASTR + c) * 2, gp);
        }
        CP_COMMIT();
    };

    issue_kv(0, 0);

    for (int kt = 0; kt <= ktmax; kt++) {
        const int s = kt & 1;
        if (kt < ktmax) { issue_kv(kt + 1, s ^ 1); CP_WAIT1(); }
        else            { CP_WAIT0(); }
        __syncthreads();

        const u32 sKh = stage0 + s * ASTG_B;
        const u32 sKl = sKh + AST_B;
        const u32 sVh = sKl + AST_B;

        // ---- S = Q @ (Kh + Kl)^T, f16 2-pass ----
        float S[8][4];
#pragma unroll
        for (int t = 0; t < 8; t++)
#pragma unroll
            for (int r = 0; r < 4; r++) S[t][r] = 0.f;

#pragma unroll
        for (int ks = 0; ks < 8; ks++) {
            u32 qa[4];
            const u32 qoff = ((wm + arow) * ASTR + ks * 16 + acolq) * 2;
            LDSM_X4(qa[0], qa[1], qa[2], qa[3], sQ + qoff);
#pragma unroll
            for (int nt2 = 0; nt2 < 4; nt2++) {
                u32 kh[4], kl[4];
                const u32 koff = ((nt2 * 16 + b4row) * ASTR + ks * 16 + b4colq) * 2;
                LDSM_X4(kh[0], kh[1], kh[2], kh[3], sKh + koff);
                LDSM_X4(kl[0], kl[1], kl[2], kl[3], sKl + koff);
                MMA16816H(S[2*nt2],   qa, kh);     MMA16816H(S[2*nt2+1], qa, kh + 2);
                MMA16816H(S[2*nt2],   qa, kl);     MMA16816H(S[2*nt2+1], qa, kl + 2);
            }
        }

        if (kt * 64 + 63 > q0 + wm) {
            const int rg0 = q0 + wm + er;
#pragma unroll
            for (int t = 0; t < 8; t++)
#pragma unroll
                for (int j = 0; j < 2; j++) {
                    const int col = kt * 64 + t * 8 + ec + j;
                    if (col > rg0)     S[t][j]     = -1e30f;
                    if (col > rg0 + 8) S[t][2 + j] = -1e30f;
                }
        }

        float mt0 = -1e30f, mt1 = -1e30f;
#pragma unroll
        for (int t = 0; t < 8; t++) {
            mt0 = fmaxf(mt0, fmaxf(S[t][0], S[t][1]));
            mt1 = fmaxf(mt1, fmaxf(S[t][2], S[t][3]));
        }
        mt0 = fmaxf(mt0, __shfl_xor_sync(0xffffffffu, mt0, 1));
        mt0 = fmaxf(mt0, __shfl_xor_sync(0xffffffffu, mt0, 2));
        mt1 = fmaxf(mt1, __shfl_xor_sync(0xffffffffu, mt1, 1));
        mt1 = fmaxf(mt1, __shfl_xor_sync(0xffffffffu, mt1, 2));
        const float mn0 = fmaxf(m0, mt0), mn1 = fmaxf(m1, mt1);
        const float a0 = __expf(m0 - mn0), a1 = __expf(m1 - mn1);
        m0 = mn0; m1 = mn1;
        La[0] *= a0; La[1] *= a0; La[2] *= a1; La[3] *= a1;
#pragma unroll
        for (int t = 0; t < 16; t++) {
            O[t][0] *= a0; O[t][1] *= a0;
            O[t][2] *= a1; O[t][3] *= a1;
        }

        const float mnl0 = mn0 * LOG2E, mnl1 = mn1 * LOG2E;
        u32 ph[8][2];
#pragma unroll
        for (int t = 0; t < 8; t++) {
            const float p0 = ex2f(fmaf(S[t][0], LOG2E, -mnl0));
            const float p1 = ex2f(fmaf(S[t][1], LOG2E, -mnl0));
            const float p2 = ex2f(fmaf(S[t][2], LOG2E, -mnl1));
            const float p3 = ex2f(fmaf(S[t][3], LOG2E, -mnl1));
            ph[t][0] = cvtf16x2(p0, p1);
            ph[t][1] = cvtf16x2(p2, p3);
        }

#pragma unroll
        for (int ks2 = 0; ks2 < 4; ks2++) {
            const u32 ah[4] = {ph[2*ks2][0], ph[2*ks2][1], ph[2*ks2+1][0], ph[2*ks2+1][1]};
            MMA16816H(La, ah, onesfrag);
#pragma unroll
            for (int nt2 = 0; nt2 < 8; nt2++) {
                u32 vh[4];
                const u32 voff = ((ks2 * 16 + (lane & 15)) * ASTR
                                  + nt2 * 16 + (lane >> 4) * 8) * 2;
                LDSM_X4T(vh[0], vh[1], vh[2], vh[3], sVh + voff);
                MMA16816H(O[2*nt2],   ah, vh);
                MMA16816H(O[2*nt2+1], ah, vh + 2);
            }
        }
        __syncthreads();
    }

    const float inv0 = 1.0f / La[0], inv1 = 1.0f / La[2];
    const size_t row0 = (size_t)(b * T_SZ + q0 + wm + er);
#pragma unroll
    for (int t = 0; t < 16; t++) {
        const int col = h * HD + t * 8 + ec;
        *(float2*)&out[row0 * C_DIM + col]       = make_float2(O[t][0] * inv0, O[t][1] * inv0);
        *(float2*)&out[(row0 + 8) * C_DIM + col] = make_float2(O[t][2] * inv1, O[t][3] * inv1);
    }
}

// ---------------- launcher: two-stream overlap (qproj || kvproj) --------------
extern "C" void kernel_launch(void* const* d_in, const int* in_sizes, int n_in,
                              void* d_out, int out_size)
{
    const float* x    = (const float*)d_in[0];
    const float* Wg   = (const float*)d_in[1];
    const float* Wqkv = (const float*)d_in[2];
    float* out = (float*)d_out;

    static cudaStream_t s2 = nullptr;
    static cudaEvent_t evF = nullptr, evX = nullptr, evQ = nullptr;
    if (s2 == nullptr) {
        cudaStreamCreateWithFlags(&s2, cudaStreamNonBlocking);
        cudaEventCreateWithFlags(&evF, cudaEventDisableTiming);
        cudaEventCreateWithFlags(&evX, cudaEventDisableTiming);
        cudaEventCreateWithFlags(&evQ, cudaEventDisableTiming);
    }

    cudaFuncSetAttribute(attn_mma_kernel, cudaFuncAttributeMaxDynamicSharedMemorySize, ATTN_SMEM);
    cudaFuncSetAttribute(qproj_mma_kernel, cudaFuncAttributeMaxDynamicSharedMemorySize, QP_SMEM);

    __half *wh, *wl;
    cudaGetSymbolAddress((void**)&wh, g_wh);
    cudaGetSymbolAddress((void**)&wl, g_wl);

    cudaEventRecord(evF, 0);
    cudaStreamWaitEvent(s2, evF, 0);

    // s2: weight f16 hi/lo conversion
    cvt_kernel<<<(C_DIM * C_DIM / 4 + 255) / 256, 256, 0, s2>>>(Wqkv, wh, wl, C_DIM * C_DIM / 4);

    // main: zero + fused x-convert/gating
    zero_kernel<<<512, 256>>>();
    xcvt_gate_kernel<<<BT / GT, 256>>>(x, Wg);
    cudaEventRecord(evX, 0);

    // s2: qproj
    cudaStreamWaitEvent(s2, evX, 0);
    qproj_mma_kernel<<<dim3(C_DIM / 128, BT / 128), 256, QP_SMEM, s2>>>();
    cudaEventRecord(evQ, s2);

    // main: kvproj + kvcvt, concurrent with qproj
    kvproj_kernel<<<dim3(128, N_HEADS, 2 * KV_SPLITS), 256>>>(x, Wqkv);
    kvcvt_kernel<<<(BT * HD / 4 + 255) / 256, 256>>>();

    // join and run attention
    cudaStreamWaitEvent(0, evQ, 0);
    attn_mma_kernel<<<dim3(16, N_HEADS, B_SZ), 256, ATTN_SMEM>>>(out);
}

// round 17
// speedup vs baseline: 1.2709x; 1.2709x over previous
#include <cuda_runtime.h>
#include <cuda_bf16.h>
#include <cuda_fp16.h>
#include <math.h>

#define C_DIM   2048
#define N_HEADS 16
#define HD      128
#define B_SZ    2
#define T_SZ    2048
#define BT      (B_SZ * T_SZ)

typedef unsigned long long u64;
typedef unsigned int u32;

#define LOG2E 1.4426950408889634f

// ---------------- packed f32x2 helpers (SASS FFMA2) -------------------------
__device__ __forceinline__ u64 pk2(float lo, float hi) {
    u64 r; asm("mov.b64 %0, {%1, %2};" : "=l"(r) : "f"(lo), "f"(hi)); return r;
}
__device__ __forceinline__ void fma2(u64& d, u64 a, u64 b) {
    asm("fma.rn.f32x2 %0, %1, %2, %0;" : "+l"(d) : "l"(a), "l"(b));
}
__device__ __forceinline__ float2 upk2(u64 v) {
    float2 f; asm("mov.b64 {%0, %1}, %2;" : "=f"(f.x), "=f"(f.y) : "l"(v)); return f;
}

// ---------------- mma.sync / ldmatrix / cp.async helpers --------------------
__device__ __forceinline__ u32 smem_u32(const void* p) {
    u32 a; asm("{ .reg .u64 t; cvta.to.shared.u64 t, %1; cvt.u32.u64 %0, t; }"
               : "=r"(a) : "l"(p));
    return a;
}
#define LDSM_X4(r0, r1, r2, r3, addr) \
    asm volatile("ldmatrix.sync.aligned.m8n8.x4.shared.b16 {%0,%1,%2,%3}, [%4];" \
        : "=r"(r0), "=r"(r1), "=r"(r2), "=r"(r3) : "r"(addr))
#define LDSM_X4T(r0, r1, r2, r3, addr) \
    asm volatile("ldmatrix.sync.aligned.m8n8.x4.trans.shared.b16 {%0,%1,%2,%3}, [%4];" \
        : "=r"(r0), "=r"(r1), "=r"(r2), "=r"(r3) : "r"(addr))
#define LDSM_X2(r0, r1, addr) \
    asm volatile("ldmatrix.sync.aligned.m8n8.x2.shared.b16 {%0,%1}, [%2];" \
        : "=r"(r0), "=r"(r1) : "r"(addr))
#define MMA16816(d, a, b) \
    asm volatile("mma.sync.aligned.m16n8k16.row.col.f32.bf16.bf16.f32 " \
        "{%0,%1,%2,%3}, {%4,%5,%6,%7}, {%8,%9}, {%0,%1,%2,%3};" \
        : "+f"((d)[0]), "+f"((d)[1]), "+f"((d)[2]), "+f"((d)[3]) \
        : "r"((a)[0]), "r"((a)[1]), "r"((a)[2]), "r"((a)[3]), "r"((b)[0]), "r"((b)[1]))
#define MMA16816H(d, a, b) \
    asm volatile("mma.sync.aligned.m16n8k16.row.col.f32.f16.f16.f32 " \
        "{%0,%1,%2,%3}, {%4,%5,%6,%7}, {%8,%9}, {%0,%1,%2,%3};" \
        : "+f"((d)[0]), "+f"((d)[1]), "+f"((d)[2]), "+f"((d)[3]) \
        : "r"((a)[0]), "r"((a)[1]), "r"((a)[2]), "r"((a)[3]), "r"((b)[0]), "r"((b)[1]))
#define CP16(daddr, gsrc) \
    asm volatile("cp.async.cg.shared.global [%0], [%1], 16;" \
        :: "r"(daddr), "l"(gsrc) : "memory")
#define CP_COMMIT() asm volatile("cp.async.commit_group;" ::: "memory")
#define CP_WAIT0()  asm volatile("cp.async.wait_group 0;" ::: "memory")
#define CP_WAIT1()  asm volatile("cp.async.wait_group 1;" ::: "memory")

__device__ __forceinline__ u32 pack_bf2(__nv_bfloat16 a, __nv_bfloat16 b) {
    __nv_bfloat162 t = __halves2bfloat162(a, b);
    return *(u32*)&t;
}
__device__ __forceinline__ float ex2f(float x) {
    float r; asm("ex2.approx.f32 %0, %1;" : "=f"(r) : "f"(x)); return r;
}
__device__ __forceinline__ u32 cvtf16x2(float lo, float hi) {
    u32 r; asm("cvt.rn.f16x2.f32 %0, %1, %2;" : "=r"(r) : "f"(hi), "f"(lo)); return r;
}

// ---------------- scratch ----------------------------------------------------
__device__ __align__(16) float g_ks[BT * HD];
__device__ __align__(16) float g_vs[BT * HD];
__device__ float g_gv [BT];
__device__ int   g_cnt[N_HEADS];
__device__ int   g_list[N_HEADS * BT];
__device__ __align__(16) __nv_bfloat16 g_xh[BT * C_DIM];
__device__ __align__(16) __nv_bfloat16 g_xl[BT * C_DIM];
__device__ __align__(16) __nv_bfloat16 g_wh[C_DIM * C_DIM];
__device__ __align__(16) __nv_bfloat16 g_wl[C_DIM * C_DIM];
__device__ __align__(16) __nv_bfloat16 g_qh[BT * C_DIM];   // scaled Q hi
__device__ __align__(16) __nv_bfloat16 g_ql[BT * C_DIM];   // scaled Q lo
__device__ __align__(16) __nv_bfloat16 g_kh[BT * HD];
__device__ __align__(16) __nv_bfloat16 g_kl[BT * HD];
__device__ __align__(16) __half        g_vh[BT * HD];      // V f16

// ---------------- K0: zero counters + K/V accumulators -----------------------
__global__ __launch_bounds__(256) void zero_kernel() {
    const int i = blockIdx.x * 256 + threadIdx.x;
    const float4 z = make_float4(0.f, 0.f, 0.f, 0.f);
    if (i < BT * HD / 4) { ((float4*)g_ks)[i] = z; ((float4*)g_vs)[i] = z; }
    if (blockIdx.x == 0 && threadIdx.x < N_HEADS) g_cnt[threadIdx.x] = 0;
}

// ---------------- K1: split fp32 -> bf16 hi/lo (Q weights) --------------------
__global__ __launch_bounds__(256) void cvt_kernel(
    const float* __restrict__ src, __nv_bfloat16* __restrict__ hi,
    __nv_bfloat16* __restrict__ lo, int n4)
{
    const int i = blockIdx.x * 256 + threadIdx.x;
    if (i >= n4) return;
    const float4 v = ((const float4*)src)[i];
    const float f[4] = {v.x, v.y, v.z, v.w};
    __nv_bfloat16 h[4], l[4];
#pragma unroll
    for (int j = 0; j < 4; j++) {
        h[j] = __float2bfloat16(f[j]);
        l[j] = __float2bfloat16(f[j] - __bfloat162float(h[j]));
    }
    u32* H = (u32*)hi; u32* L = (u32*)lo;
    H[2*i]   = pack_bf2(h[0], h[1]);
    H[2*i+1] = pack_bf2(h[2], h[3]);
    L[2*i]   = pack_bf2(l[0], l[1]);
    L[2*i+1] = pack_bf2(l[2], l[3]);
}

// ---------------- K2: fused x hi/lo conversion + gating -----------------------
#define GT   16
#define XSTR 144

__global__ __launch_bounds__(256) void xcvt_gate_kernel(
    const float* __restrict__ x, const float* __restrict__ Wg)
{
    __shared__ float Xs[GT * XSTR];
    __shared__ float Ws[16 * 128];
    const int tid = threadIdx.x;
    const int t0 = blockIdx.x * GT;

    float acc[N_HEADS];
#pragma unroll
    for (int h = 0; h < N_HEADS; h++) acc[h] = 0.0f;

    for (int kc = 0; kc < C_DIM / 128; kc++) {
        __syncthreads();
        for (int u = tid; u < 512; u += 256) {
            const int h = u >> 5, c4 = u & 31;
            *(float4*)&Ws[h * 128 + c4 * 4] =
                *(const float4*)&Wg[(size_t)h * C_DIM + kc * 128 + c4 * 4];
        }
        for (int u = tid; u < GT * 32; u += 256) {
            const int r = u >> 5, c4 = u & 31;
            const size_t g = (size_t)(t0 + r) * C_DIM + kc * 128 + c4 * 4;
            const float4 v = *(const float4*)&x[g];
            *(float4*)&Xs[r * XSTR + c4 * 4] = v;
            const float f[4] = {v.x, v.y, v.z, v.w};
            __nv_bfloat16 h_[4], l_[4];
#pragma unroll
            for (int j = 0; j < 4; j++) {
                h_[j] = __float2bfloat16(f[j]);
                l_[j] = __float2bfloat16(f[j] - __bfloat162float(h_[j]));
            }
            ((u32*)&g_xh[g])[0] = pack_bf2(h_[0], h_[1]);
            ((u32*)&g_xh[g])[1] = pack_bf2(h_[2], h_[3]);
            ((u32*)&g_xl[g])[0] = pack_bf2(l_[0], l_[1]);
            ((u32*)&g_xl[g])[1] = pack_bf2(l_[2], l_[3]);
        }
        __syncthreads();
        const int r = tid >> 4, i = tid & 15;
#pragma unroll
        for (int k = 0; k < 8; k++) {
            const float xv = Xs[r * XSTR + k * 16 + i];
#pragma unroll
            for (int h = 0; h < N_HEADS; h++)
                acc[h] += xv * Ws[h * 128 + k * 16 + i];
        }
    }
#pragma unroll
    for (int off = 1; off < 16; off <<= 1) {
#pragma unroll
        for (int h = 0; h < N_HEADS; h++)
            acc[h] += __shfl_xor_sync(0xffffffffu, acc[h], off);
    }
    if ((tid & 15) == 0) {
        const int t = t0 + (tid >> 4);
        float mx = acc[0]; int bi = 0;
#pragma unroll
        for (int h = 1; h < N_HEADS; h++)
            if (acc[h] > mx) { mx = acc[h]; bi = h; }
        float s = 0.0f;
#pragma unroll
        for (int h = 0; h < N_HEADS; h++) s += expf(acc[h] - mx);
        g_gv[t] = 1.0f / s;
        const int pos = atomicAdd(&g_cnt[bi], 1);
        g_list[bi * BT + pos] = t;
    }
}

// ---------------- K3: Q projection, mma.sync + cp.async double-buffer ---------
#define QSTR 40
#define QP_SZ   (128 * QSTR)
#define QP_SZB  (QP_SZ * 2)
#define QP_STAGEB (4 * QP_SZB)
#define QP_SMEM (2 * QP_STAGEB)

__global__ __launch_bounds__(256, 2) void qproj_mma_kernel()
{
    extern __shared__ __nv_bfloat16 qsm[];
    const u32 sb = smem_u32(qsm);

    const int tid = threadIdx.x, lane = tid & 31, wid = tid >> 5;
    const int wm = (wid >> 2) * 64;
    const int wn = (wid & 3) * 32;
    const int m0 = blockIdx.y * 128, n0 = blockIdx.x * 128;

    float acc[4][4][4];
#pragma unroll
    for (int i = 0; i < 4; i++)
#pragma unroll
        for (int j = 0; j < 4; j++)
#pragma unroll
            for (int r = 0; r < 4; r++) acc[i][j][r] = 0.0f;

    const int q = lane >> 3, r8 = lane & 7;
    const int arow = (q & 1) * 8 + r8, acolq = (q >> 1) * 8;
    const int l2 = lane & 15;
    const int brow = l2 & 7, bcolq = (l2 >> 3) * 8;

    auto issue_stage = [&](int kt, int s) {
#pragma unroll
        for (int v = 0; v < 8; v++) {
            const int u = tid + v * 256;
            const int arr = u >> 9;
            const int rr = (u >> 2) & 127;
            const int cc = (u & 3) * 8;
            const __nv_bfloat16* gp;
            if (arr == 0)      gp = g_xh + (size_t)(m0 + rr) * C_DIM + kt + cc;
            else if (arr == 1) gp = g_xl + (size_t)(m0 + rr) * C_DIM + kt + cc;
            else if (arr == 2) gp = g_wh + (size_t)(n0 + rr) * C_DIM + kt + cc;
            else               gp = g_wl + (size_t)(n0 + rr) * C_DIM + kt + cc;
            const u32 da = sb + s * QP_STAGEB + arr * QP_SZB + (rr * QSTR + cc) * 2;
            CP16(da, gp);
        }
        CP_COMMIT();
    };

    issue_stage(0, 0);

    const int NIT = C_DIM / 32;
    for (int i = 0; i < NIT; i++) {
        const int s = i & 1;
        if (i + 1 < NIT) { issue_stage((i + 1) * 32, s ^ 1); CP_WAIT1(); }
        else             { CP_WAIT0(); }
        __syncthreads();

        const u32 sAh = sb + s * QP_STAGEB;
        const u32 sAl = sAh + QP_SZB;
        const u32 sBh = sAl + QP_SZB;
        const u32 sBl = sBh + QP_SZB;

#pragma unroll
        for (int ks = 0; ks < 2; ks++) {
            const int acol = ks * 16 + acolq;
            const int bcol = ks * 16 + bcolq;
            u32 a_hi[4][4], a_lo[4][4], b_hi[4][2], b_lo[4][2];
#pragma unroll
            for (int mt = 0; mt < 4; mt++) {
                const u32 off = ((wm + mt * 16 + arow) * QSTR + acol) * 2;
                LDSM_X4(a_hi[mt][0], a_hi[mt][1], a_hi[mt][2], a_hi[mt][3], sAh + off);
                LDSM_X4(a_lo[mt][0], a_lo[mt][1], a_lo[mt][2], a_lo[mt][3], sAl + off);
            }
#pragma unroll
            for (int nt = 0; nt < 4; nt++) {
                const u32 off = ((wn + nt * 8 + brow) * QSTR + bcol) * 2;
                LDSM_X2(b_hi[nt][0], b_hi[nt][1], sBh + off);
                LDSM_X2(b_lo[nt][0], b_lo[nt][1], sBl + off);
            }
#pragma unroll
            for (int mt = 0; mt < 4; mt++)
#pragma unroll
                for (int nt = 0; nt < 4; nt++) {
                    MMA16816(acc[mt][nt], a_hi[mt], b_hi[nt]);
                    MMA16816(acc[mt][nt], a_hi[mt], b_lo[nt]);
                    MMA16816(acc[mt][nt], a_lo[mt], b_hi[nt]);
                }
        }
        __syncthreads();
    }

    const float SC = 0.08838834764831845f;  // 1/sqrt(128)
    const int er = lane >> 2, ec = (lane & 3) * 2;
#pragma unroll
    for (int mt = 0; mt < 4; mt++) {
        const size_t row = (size_t)(m0 + wm + mt * 16 + er);
#pragma unroll
        for (int nt = 0; nt < 4; nt++) {
            const int col = n0 + wn + nt * 8 + ec;
#pragma unroll
            for (int half = 0; half < 2; half++) {
                const float v0 = acc[mt][nt][half * 2 + 0] * SC;
                const float v1 = acc[mt][nt][half * 2 + 1] * SC;
                const __nv_bfloat16 h0 = __float2bfloat16(v0);
                const __nv_bfloat16 h1 = __float2bfloat16(v1);
                const __nv_bfloat16 e0 = __float2bfloat16(v0 - __bfloat162float(h0));
                const __nv_bfloat16 e1 = __float2bfloat16(v1 - __bfloat162float(h1));
                const size_t o = (row + half * 8) * C_DIM + col;
                *(u32*)&g_qh[o] = pack_bf2(h0, h1);
                *(u32*)&g_ql[o] = pack_bf2(e0, e1);
            }
        }
    }
}

// ---------------- K4: grouped K/V projection, split-K=4 + atomics -------------
#define KV_SPLITS 4
#define KV_KCH (C_DIM / KV_SPLITS)

__global__ __launch_bounds__(256) void kvproj_kernel(
    const float* __restrict__ x, const float* __restrict__ Wqkv)
{
    const int h = blockIdx.y;
    const int kv = blockIdx.z & 1, sp = blockIdx.z >> 1;
    const int cnt = g_cnt[h];
    const int m0 = blockIdx.x * 32;
    if (m0 >= cnt) return;

    __shared__ float As[16][32];
    __shared__ float Bs[16][128];
    const int tid = threadIdx.x;
    const int blr = tid >> 2, blc = (tid & 3) << 2;
    const int tx = tid & 31, ty = tid >> 5;

    const int* lst = g_list + h * BT;
    int tokA = 0;
    if (tid < 128) tokA = lst[min(m0 + (tid >> 2), cnt - 1)];
    const float* Bp = Wqkv + (size_t)(C_DIM * (1 + kv) + h * HD) * C_DIM;

    u64 acc2[4][2];
#pragma unroll
    for (int i = 0; i < 4; i++) { acc2[i][0] = 0ULL; acc2[i][1] = 0ULL; }

    const int k0 = sp * KV_KCH;
    for (int kt = k0; kt < k0 + KV_KCH; kt += 16) {
        float4 a0 = make_float4(0.f, 0.f, 0.f, 0.f);
        if (tid < 128)
            a0 = *(const float4*)(x + (size_t)tokA * C_DIM + kt + blc);
        const float4 b0 = *(const float4*)(Bp + (size_t)blr        * C_DIM + kt + blc);
        const float4 b1 = *(const float4*)(Bp + (size_t)(blr + 64) * C_DIM + kt + blc);
        __syncthreads();
        if (tid < 128) {
            const int ar = tid >> 2;
            As[blc+0][ar] = a0.x; As[blc+1][ar] = a0.y;
            As[blc+2][ar] = a0.z; As[blc+3][ar] = a0.w;
        }
        Bs[blc+0][blr] = b0.x; Bs[blc+1][blr] = b0.y; Bs[blc+2][blr] = b0.z; Bs[blc+3][blr] = b0.w;
        Bs[blc+0][blr+64] = b1.x; Bs[blc+1][blr+64] = b1.y; Bs[blc+2][blr+64] = b1.z; Bs[blc+3][blr+64] = b1.w;
        __syncthreads();
#pragma unroll
        for (int k = 0; k < 16; k++) {
            const float4 av = *(const float4*)&As[k][ty * 4];
            const float4 bv = *(const float4*)&Bs[k][tx * 4];
            const u64 b20 = pk2(bv.x, bv.y), b21 = pk2(bv.z, bv.w);
            const float aa[4] = {av.x, av.y, av.z, av.w};
#pragma unroll
            for (int i = 0; i < 4; i++) {
                const u64 a2 = pk2(aa[i], aa[i]);
                fma2(acc2[i][0], a2, b20);
                fma2(acc2[i][1], a2, b21);
            }
        }
    }
    float* dst = kv ? g_vs : g_ks;
#pragma unroll
    for (int i = 0; i < 4; i++) {
        const int m = m0 + ty * 4 + i;
        if (m < cnt) {
            const int tok = lst[m];
            const float sc = kv ? g_gv[tok] : 1.0f;
            const float2 c0 = upk2(acc2[i][0]), c1 = upk2(acc2[i][1]);
            float* d = dst + (size_t)tok * HD + tx * 4;
            atomicAdd(d + 0, c0.x * sc);
            atomicAdd(d + 1, c0.y * sc);
            atomicAdd(d + 2, c1.x * sc);
            atomicAdd(d + 3, c1.y * sc);
        }
    }
}

// ---------------- K4b: K fp32 -> bf16 hi/lo ; V fp32 -> f16 -------------------
__global__ __launch_bounds__(256) void kvcvt_kernel() {
    const int i = blockIdx.x * 256 + threadIdx.x;
    if (i >= BT * HD / 4) return;
    {
        const float4 v = ((const float4*)g_ks)[i];
        const float f[4] = {v.x, v.y, v.z, v.w};
        __nv_bfloat16 h[4], l[4];
#pragma unroll
        for (int j = 0; j < 4; j++) {
            h[j] = __float2bfloat16(f[j]);
            l[j] = __float2bfloat16(f[j] - __bfloat162float(h[j]));
        }
        ((u32*)g_kh)[2*i]   = pack_bf2(h[0], h[1]);
        ((u32*)g_kh)[2*i+1] = pack_bf2(h[2], h[3]);
        ((u32*)g_kl)[2*i]   = pack_bf2(l[0], l[1]);
        ((u32*)g_kl)[2*i+1] = pack_bf2(l[2], l[3]);
    }
    {
        const float4 v = ((const float4*)g_vs)[i];
        ((u32*)g_vh)[2*i]   = cvtf16x2(v.x, v.y);
        ((u32*)g_vh)[2*i+1] = cvtf16x2(v.z, v.w);
    }
}

// ---------------- K5: tensor-core causal flash MQA attention ------------------
// BQ=128, 8 warps, BK=64, cp.async double-buffered K/V.
// S: bf16 hi/lo 3-pass (Q-hi fragments hoisted to registers). P: f16. V: f16.
#define ASTR 136
#define AQ_B   (128 * ASTR * 2)
#define AST_B  (64 * ASTR * 2)
#define ASTG_B (3 * AST_B)
#define ATTN_SMEM (2 * AQ_B + 2 * ASTG_B)

__global__ __launch_bounds__(256, 1) void attn_mma_kernel(float* __restrict__ out)
{
    extern __shared__ char sbuf[];
    const u32 sb = smem_u32(sbuf);
    const u32 sQh = sb, sQl = sb + AQ_B;
    const u32 stage0 = sb + 2 * AQ_B;

    const int b  = blockIdx.z, h = blockIdx.y;
    const int qt = gridDim.x - 1 - blockIdx.x;
    const int q0 = qt * 128;
    const int tid = threadIdx.x, lane = tid & 31, wid = tid >> 5;
    const int wm = wid * 16;

    for (int u = tid; u < 2048; u += 256) {
        const int r = u >> 4, c = (u & 15) * 8;
        const size_t g = (size_t)(b * T_SZ + q0 + r) * C_DIM + h * HD + c;
        *(uint4*)(sbuf + (r * ASTR + c) * 2)        = *(const uint4*)&g_qh[g];
        *(uint4*)(sbuf + AQ_B + (r * ASTR + c) * 2) = *(const uint4*)&g_ql[g];
    }

    const int qq = lane >> 3, r8 = lane & 7;
    const int arow = (qq & 1) * 8 + r8, acolq = (qq >> 1) * 8;
    const int b4row = (lane >> 4) * 8 + (lane & 7);
    const int b4colq = ((lane >> 3) & 1) * 8;
    const int er = lane >> 2, ec = (lane & 3) * 2;

    // ---- hoist Q-hi fragments (constant across the whole main loop) ----
    __syncthreads();
    u32 qhf[8][4];
#pragma unroll
    for (int ks = 0; ks < 8; ks++) {
        const u32 qoff = ((wm + arow) * ASTR + ks * 16 + acolq) * 2;
        LDSM_X4(qhf[ks][0], qhf[ks][1], qhf[ks][2], qhf[ks][3], sQh + qoff);
    }

    float m0 = -1e30f, m1 = -1e30f;
    float La[4] = {0.f, 0.f, 0.f, 0.f};
    float O[16][4];
#pragma unroll
    for (int t = 0; t < 16; t++)
#pragma unroll
        for (int r = 0; r < 4; r++) O[t][r] = 0.f;

    const u32 ones2 = 0x3C003C00u;
    const u32 onesfrag[2] = {ones2, ones2};

    const int ktmax = 2 * qt + 1;

    auto issue_kv = [&](int kt, int s) {
#pragma unroll
        for (int v = 0; v < 12; v++) {
            const int u = tid + v * 256;
            const int arr = u >> 10;
            const int idx = u & 1023;
            const int r = idx >> 4, c = (idx & 15) * 8;
            const size_t g = (size_t)(b * T_SZ + kt * 64 + r) * HD + c;
            const void* gp = (arr == 0) ? (const void*)&g_kh[g]
                           : (arr == 1) ? (const void*)&g_kl[g]
                                        : (const void*)&g_vh[g];
            CP16(stage0 + s * ASTG_B + arr * AST_B + (r * ASTR + c) * 2, gp);
        }
        CP_COMMIT();
    };

    issue_kv(0, 0);

    for (int kt = 0; kt <= ktmax; kt++) {
        const int s = kt & 1;
        if (kt < ktmax) { issue_kv(kt + 1, s ^ 1); CP_WAIT1(); }
        else            { CP_WAIT0(); }
        __syncthreads();

        const u32 sKh = stage0 + s * ASTG_B;
        const u32 sKl = sKh + AST_B;
        const u32 sVh = sKl + AST_B;

        float S[8][4];
#pragma unroll
        for (int t = 0; t < 8; t++)
#pragma unroll
            for (int r = 0; r < 4; r++) S[t][r] = 0.f;

#pragma unroll
        for (int ks = 0; ks < 8; ks++) {
            u32 ql[4];
            const u32 qoff = ((wm + arow) * ASTR + ks * 16 + acolq) * 2;
            LDSM_X4(ql[0], ql[1], ql[2], ql[3], sQl + qoff);
#pragma unroll
            for (int nt2 = 0; nt2 < 4; nt2++) {
                u32 kh[4], kl[4];
                const u32 koff = ((nt2 * 16 + b4row) * ASTR + ks * 16 + b4colq) * 2;
                LDSM_X4(kh[0], kh[1], kh[2], kh[3], sKh + koff);
                LDSM_X4(kl[0], kl[1], kl[2], kl[3], sKl + koff);
                MMA16816(S[2*nt2],   qhf[ks], kh);     MMA16816(S[2*nt2+1], qhf[ks], kh + 2);
                MMA16816(S[2*nt2],   qhf[ks], kl);     MMA16816(S[2*nt2+1], qhf[ks], kl + 2);
                MMA16816(S[2*nt2],   ql,      kh);     MMA16816(S[2*nt2+1], ql,      kh + 2);
            }
        }

        if (kt * 64 + 63 > q0 + wm) {
            const int rg0 = q0 + wm + er;
#pragma unroll
            for (int t = 0; t < 8; t++)
#pragma unroll
                for (int j = 0; j < 2; j++) {
                    const int col = kt * 64 + t * 8 + ec + j;
                    if (col > rg0)     S[t][j]     = -1e30f;
                    if (col > rg0 + 8) S[t][2 + j] = -1e30f;
                }
        }

        float mt0 = -1e30f, mt1 = -1e30f;
#pragma unroll
        for (int t = 0; t < 8; t++) {
            mt0 = fmaxf(mt0, fmaxf(S[t][0], S[t][1]));
            mt1 = fmaxf(mt1, fmaxf(S[t][2], S[t][3]));
        }
        mt0 = fmaxf(mt0, __shfl_xor_sync(0xffffffffu, mt0, 1));
        mt0 = fmaxf(mt0, __shfl_xor_sync(0xffffffffu, mt0, 2));
        mt1 = fmaxf(mt1, __shfl_xor_sync(0xffffffffu, mt1, 1));
        mt1 = fmaxf(mt1, __shfl_xor_sync(0xffffffffu, mt1, 2));
        const float mn0 = fmaxf(m0, mt0), mn1 = fmaxf(m1, mt1);
        const float a0 = __expf(m0 - mn0), a1 = __expf(m1 - mn1);
        m0 = mn0; m1 = mn1;
        La[0] *= a0; La[1] *= a0; La[2] *= a1; La[3] *= a1;
#pragma unroll
        for (int t = 0; t < 16; t++) {
            O[t][0] *= a0; O[t][1] *= a0;
            O[t][2] *= a1; O[t][3] *= a1;
        }

        const float mnl0 = mn0 * LOG2E, mnl1 = mn1 * LOG2E;
        u32 ph[8][2];
#pragma unroll
        for (int t = 0; t < 8; t++) {
            const float p0 = ex2f(fmaf(S[t][0], LOG2E, -mnl0));
            const float p1 = ex2f(fmaf(S[t][1], LOG2E, -mnl0));
            const float p2 = ex2f(fmaf(S[t][2], LOG2E, -mnl1));
            const float p3 = ex2f(fmaf(S[t][3], LOG2E, -mnl1));
            ph[t][0] = cvtf16x2(p0, p1);
            ph[t][1] = cvtf16x2(p2, p3);
        }

#pragma unroll
        for (int ks2 = 0; ks2 < 4; ks2++) {
            const u32 ah[4] = {ph[2*ks2][0], ph[2*ks2][1], ph[2*ks2+1][0], ph[2*ks2+1][1]};
            MMA16816H(La, ah, onesfrag);
#pragma unroll
            for (int nt2 = 0; nt2 < 8; nt2++) {
                u32 vh[4];
                const u32 voff = ((ks2 * 16 + (lane & 15)) * ASTR
                                  + nt2 * 16 + (lane >> 4) * 8) * 2;
                LDSM_X4T(vh[0], vh[1], vh[2], vh[3], sVh + voff);
                MMA16816H(O[2*nt2],   ah, vh);
                MMA16816H(O[2*nt2+1], ah, vh + 2);
            }
        }
        __syncthreads();
    }

    const float inv0 = 1.0f / La[0], inv1 = 1.0f / La[2];
    const size_t row0 = (size_t)(b * T_SZ + q0 + wm + er);
#pragma unroll
    for (int t = 0; t < 16; t++) {
        const int col = h * HD + t * 8 + ec;
        *(float2*)&out[row0 * C_DIM + col]       = make_float2(O[t][0] * inv0, O[t][1] * inv0);
        *(float2*)&out[(row0 + 8) * C_DIM + col] = make_float2(O[t][2] * inv1, O[t][3] * inv1);
    }
}

// ---------------- launcher: two-stream overlap (qproj || kvproj) --------------
extern "C" void kernel_launch(void* const* d_in, const int* in_sizes, int n_in,
                              void* d_out, int out_size)
{
    const float* x    = (const float*)d_in[0];
    const float* Wg   = (const float*)d_in[1];
    const float* Wqkv = (const float*)d_in[2];
    float* out = (float*)d_out;

    static cudaStream_t s2 = nullptr;
    static cudaEvent_t evF = nullptr, evX = nullptr, evQ = nullptr;
    if (s2 == nullptr) {
        cudaStreamCreateWithFlags(&s2, cudaStreamNonBlocking);
        cudaEventCreateWithFlags(&evF, cudaEventDisableTiming);
        cudaEventCreateWithFlags(&evX, cudaEventDisableTiming);
        cudaEventCreateWithFlags(&evQ, cudaEventDisableTiming);
    }

    cudaFuncSetAttribute(attn_mma_kernel, cudaFuncAttributeMaxDynamicSharedMemorySize, ATTN_SMEM);
    cudaFuncSetAttribute(qproj_mma_kernel, cudaFuncAttributeMaxDynamicSharedMemorySize, QP_SMEM);

    __nv_bfloat16 *wh, *wl;
    cudaGetSymbolAddress((void**)&wh, g_wh);
    cudaGetSymbolAddress((void**)&wl, g_wl);

    cudaEventRecord(evF, 0);
    cudaStreamWaitEvent(s2, evF, 0);

    // s2: weight hi/lo conversion
    cvt_kernel<<<(C_DIM * C_DIM / 4 + 255) / 256, 256, 0, s2>>>(Wqkv, wh, wl, C_DIM * C_DIM / 4);

    // main: zero + fused x-convert/gating
    zero_kernel<<<512, 256>>>();
    xcvt_gate_kernel<<<BT / GT, 256>>>(x, Wg);
    cudaEventRecord(evX, 0);

    // s2: qproj
    cudaStreamWaitEvent(s2, evX, 0);
    qproj_mma_kernel<<<dim3(C_DIM / 128, BT / 128), 256, QP_SMEM, s2>>>();
    cudaEventRecord(evQ, s2);

    // main: kvproj + kvcvt, concurrent with qproj
    kvproj_kernel<<<dim3(128, N_HEADS, 2 * KV_SPLITS), 256>>>(x, Wqkv);
    kvcvt_kernel<<<(BT * HD / 4 + 255) / 256, 256>>>();

    // join and run attention
    cudaStreamWaitEvent(0, evQ, 0);
    attn_mma_kernel<<<dim3(16, N_HEADS, B_SZ), 256, ATTN_SMEM>>>(out);
}